// round 10
// baseline (speedup 1.0000x reference)
#include <cuda_runtime.h>
#include <cuda_bf16.h>
#include <math.h>
#include <stdint.h>

#define LNUM 2
#define IN_DIM 172
#define HID 128
#define NH 4
#define HD 32
#define TD 100
#define TDP 128
#define NMAX 150016
#define EMAX 500224
#define BMAX 16384

#define ID_Q    1
#define ID_K    2
#define ID_V    3
#define ID_OUT  4
#define ID_Z1   5
#define ID_Z2   6
#define ID_SUMS 8
#define ID_HH   9
#define ID_HL   10
#define ID_Z1H  11
#define ID_Z1L  12

// ---------------- scratch (static device memory; no cudaMalloc allowed) ----------------
__device__ float  g_q  [(size_t)NMAX * HID];
__device__ float  g_k  [(size_t)NMAX * HID];
__device__ float  g_v  [(size_t)NMAX * HID];
__device__ float  g_out[(size_t)NMAX * HID];
__device__ float  g_e  [(size_t)EMAX * HID];   // v[src] + e  per edge
__device__ float  g_a  [(size_t)EMAX * NH];
__device__ float  g_z1 [(size_t)BMAX * HID];
__device__ float  g_z2 [(size_t)BMAX * (HID/2)];
__device__ __nv_bfloat16 g_hh [(size_t)NMAX * HID];
__device__ __nv_bfloat16 g_hl [(size_t)NMAX * HID];
__device__ __nv_bfloat16 g_z1h[(size_t)BMAX * HID];
__device__ __nv_bfloat16 g_z1l[(size_t)BMAX * HID];
__device__ __align__(16) uint32_t g_wph[(TDP/2) * HID];
__device__ __align__(16) uint32_t g_wpl[(TDP/2) * HID];
__device__ int    g_deg  [NMAX];
__device__ int    g_start[NMAX];
__device__ int    g_cur  [NMAX];
__device__ int    g_eidx [EMAX];
__device__ double g_sums[256];
__device__ float  g_bnp[256];

__device__ __forceinline__ float* bufptr(int id) {
    switch (id) {
        case ID_Q:    return g_q;
        case ID_K:    return g_k;
        case ID_V:    return g_v;
        case ID_OUT:  return g_out;
        case ID_Z1:   return g_z1;
        case ID_Z2:   return g_z2;
        case ID_SUMS: return (float*)g_sums;
    }
    return nullptr;
}

__device__ __forceinline__ __nv_bfloat16* bufptr16(int id) {
    switch (id) {
        case ID_HH:  return g_hh;
        case ID_HL:  return g_hl;
        case ID_Z1H: return g_z1h;
        case ID_Z1L: return g_z1l;
    }
    return nullptr;
}

// ---------------- bf16 hi/lo split helpers ----------------
__device__ __forceinline__ void bsplit(float x, float y, uint32_t& hi, uint32_t& lo) {
    __nv_bfloat162 h;
    h.x = __float2bfloat16_rn(x);
    h.y = __float2bfloat16_rn(y);
    hi = *reinterpret_cast<uint32_t*>(&h);
    __nv_bfloat162 l;
    l.x = __float2bfloat16_rn(x - __bfloat162float(h.x));
    l.y = __float2bfloat16_rn(y - __bfloat162float(h.y));
    lo = *reinterpret_cast<uint32_t*>(&l);
}

__device__ __forceinline__ void mma_bf16(float* c, const uint32_t* a, const uint32_t* b) {
    asm volatile(
        "mma.sync.aligned.m16n8k16.row.col.f32.bf16.bf16.f32 "
        "{%0,%1,%2,%3}, {%4,%5,%6,%7}, {%8,%9}, {%0,%1,%2,%3};\n"
        : "+f"(c[0]), "+f"(c[1]), "+f"(c[2]), "+f"(c[3])
        : "r"(a[0]), "r"(a[1]), "r"(a[2]), "r"(a[3]), "r"(b[0]), "r"(b[1]));
}

// ---------------- generic tensor-core GEMM (gather GEMM, W1, W2) ----------------
template <int NC, bool PRESPLIT>
__global__ void __launch_bounds__(256, 2)
gemm_tc(const float* __restrict__ Aext, int AhId, int AlId, const int* __restrict__ gather,
        int M, int K, const float* __restrict__ W, const float* __restrict__ bias,
        int Cid, int relu, int ChId, int ClId)
{
    constexpr int BM = 128, BK = 32, K2 = 16;
    constexpr int AP = 20;
    constexpr int WP = NC + 8;
    constexpr int WN = NC / 2;
    constexpr int NT = WN / 8;
    constexpr int MT = 2;

    __shared__ uint32_t Ah[BM][AP], Al[BM][AP];
    __shared__ uint32_t Wh[K2][WP], Wl[K2][WP];

    const int tid  = threadIdx.x;
    const int warp = tid >> 5, lane = tid & 31;
    const int wm = warp >> 1, wn = warp & 1;
    const int lr = lane >> 2, lc = lane & 3;
    const int row0 = blockIdx.x * BM;

    float acc[MT][NT][4];
    #pragma unroll
    for (int mt = 0; mt < MT; mt++)
        #pragma unroll
        for (int nt = 0; nt < NT; nt++)
            #pragma unroll
            for (int j = 0; j < 4; j++) acc[mt][nt][j] = 0.f;

    for (int k0 = 0; k0 < K; k0 += BK) {
        if (PRESPLIT) {
            const __nv_bfloat16* AH = bufptr16(AhId);
            const __nv_bfloat16* AL = bufptr16(AlId);
            #pragma unroll
            for (int i = 0; i < 4; i++) {
                int task = tid + i * 256;
                int arr = task >> 9;
                int r   = (task >> 2) & 127;
                int u   = task & 3;
                int grow = row0 + r;
                uint4 val = make_uint4(0u, 0u, 0u, 0u);
                const __nv_bfloat16* base = arr ? AL : AH;
                if (grow < M)
                    val = *(const uint4*)(base + (size_t)grow * K + k0 + u * 8);
                *(uint4*)&((arr ? Al : Ah)[r][u * 4]) = val;
            }
        } else {
            #pragma unroll
            for (int i = 0; i < 4; i++) {
                int task = tid + i * 256;
                int r  = task >> 3;
                int kg = task & 7;
                int k  = k0 + kg * 4;
                float4 v = make_float4(0.f, 0.f, 0.f, 0.f);
                int grow = row0 + r;
                if (grow < M) {
                    long long ar = gather ? (long long)gather[grow] : (long long)grow;
                    const float* ap = Aext + ar * K + k;
                    if (k + 4 <= K) v = *(const float4*)ap;
                    else {
                        if (k     < K) v.x = ap[0];
                        if (k + 1 < K) v.y = ap[1];
                        if (k + 2 < K) v.z = ap[2];
                        if (k + 3 < K) v.w = ap[3];
                    }
                }
                uint32_t h0, l0, h1, l1;
                bsplit(v.x, v.y, h0, l0);
                bsplit(v.z, v.w, h1, l1);
                *(uint2*)&Ah[r][kg * 2] = make_uint2(h0, h1);
                *(uint2*)&Al[r][kg * 2] = make_uint2(l0, l1);
            }
        }
        #pragma unroll
        for (int i = 0; i < (K2 * NC / 4) / 256; i++) {
            int task = tid + i * 256;
            int kk = task / (NC / 4);
            int n  = (task % (NC / 4)) * 4;
            int k  = k0 + kk * 2;
            float4 r0 = make_float4(0.f,0.f,0.f,0.f), r1 = make_float4(0.f,0.f,0.f,0.f);
            if (k     < K) r0 = *(const float4*)(W + (size_t)k * NC + n);
            if (k + 1 < K) r1 = *(const float4*)(W + (size_t)(k + 1) * NC + n);
            uint4 vh, vl;
            bsplit(r0.x, r1.x, vh.x, vl.x);
            bsplit(r0.y, r1.y, vh.y, vl.y);
            bsplit(r0.z, r1.z, vh.z, vl.z);
            bsplit(r0.w, r1.w, vh.w, vl.w);
            *(uint4*)&Wh[kk][n] = vh;
            *(uint4*)&Wl[kk][n] = vl;
        }
        __syncthreads();

        #pragma unroll
        for (int ks = 0; ks < 2; ks++) {
            const int kb = ks * 8;
            uint32_t ah[MT][4], al[MT][4];
            #pragma unroll
            for (int mt = 0; mt < MT; mt++) {
                int m = wm * 32 + mt * 16 + lr;
                ah[mt][0] = Ah[m    ][kb + lc];
                ah[mt][1] = Ah[m + 8][kb + lc];
                ah[mt][2] = Ah[m    ][kb + lc + 4];
                ah[mt][3] = Ah[m + 8][kb + lc + 4];
                al[mt][0] = Al[m    ][kb + lc];
                al[mt][1] = Al[m + 8][kb + lc];
                al[mt][2] = Al[m    ][kb + lc + 4];
                al[mt][3] = Al[m + 8][kb + lc + 4];
            }
            #pragma unroll
            for (int nt = 0; nt < NT; nt++) {
                int n = wn * WN + nt * 8 + lr;
                uint32_t bh[2], bl[2];
                bh[0] = Wh[kb + lc    ][n];
                bh[1] = Wh[kb + lc + 4][n];
                bl[0] = Wl[kb + lc    ][n];
                bl[1] = Wl[kb + lc + 4][n];
                #pragma unroll
                for (int mt = 0; mt < MT; mt++) {
                    mma_bf16(acc[mt][nt], ah[mt], bh);
                    mma_bf16(acc[mt][nt], al[mt], bh);
                    mma_bf16(acc[mt][nt], ah[mt], bl);
                }
            }
        }
        __syncthreads();
    }

    float* C = (Cid >= 0) ? bufptr(Cid) : nullptr;
    __nv_bfloat16* CH = (ChId >= 0) ? bufptr16(ChId) : nullptr;
    __nv_bfloat16* CL = (ChId >= 0) ? bufptr16(ClId) : nullptr;
    #pragma unroll
    for (int mt = 0; mt < MT; mt++) {
        int rA = row0 + wm * 32 + mt * 16 + lr;
        #pragma unroll
        for (int nt = 0; nt < NT; nt++) {
            int col = wn * WN + nt * 8 + lc * 2;
            float b0 = bias[col], b1 = bias[col + 1];
            float2 v0 = make_float2(acc[mt][nt][0] + b0, acc[mt][nt][1] + b1);
            float2 v1 = make_float2(acc[mt][nt][2] + b0, acc[mt][nt][3] + b1);
            if (relu) {
                v0.x = fmaxf(v0.x, 0.f); v0.y = fmaxf(v0.y, 0.f);
                v1.x = fmaxf(v1.x, 0.f); v1.y = fmaxf(v1.y, 0.f);
            }
            #pragma unroll
            for (int half = 0; half < 2; half++) {
                int r = rA + half * 8;
                if (r >= M) continue;
                float2 v = half ? v1 : v0;
                size_t idx = (size_t)r * NC + col;
                if (C) *(float2*)&C[idx] = v;
                if (CH) {
                    __nv_bfloat16 h0 = __float2bfloat16_rn(v.x);
                    __nv_bfloat16 h1 = __float2bfloat16_rn(v.y);
                    CH[idx]     = h0;
                    CH[idx + 1] = h1;
                    CL[idx]     = __float2bfloat16_rn(v.x - __bfloat162float(h0));
                    CL[idx + 1] = __float2bfloat16_rn(v.y - __bfloat162float(h1));
                }
            }
        }
    }
}

// ---------------- fused Q/K/V/skip GEMM: A (K=128) loaded to smem ONCE ----------------
#define QKVS_A1   34816
#define QKVS_W0   69632
#define QKVS_W1B  (QKVS_W0 + 16*136*4)
#define QKVS_TOTAL (QKVS_W1B + 16*136*4)

__global__ void __launch_bounds__(256, 2)
gemm_qkvs(int M,
          const float* __restrict__ Wq, const float* __restrict__ Wk,
          const float* __restrict__ Wv, const float* __restrict__ Ws,
          const float* __restrict__ bq, const float* __restrict__ bk,
          const float* __restrict__ bv, const float* __restrict__ bs)
{
    extern __shared__ char sm[];
    uint32_t (*Ah)[68]  = (uint32_t(*)[68])sm;
    uint32_t (*Al)[68]  = (uint32_t(*)[68])(sm + QKVS_A1);
    uint32_t (*Wh)[136] = (uint32_t(*)[136])(sm + QKVS_W0);
    uint32_t (*Wl)[136] = (uint32_t(*)[136])(sm + QKVS_W1B);

    const int tid  = threadIdx.x;
    const int warp = tid >> 5, lane = tid & 31;
    const int wm = warp >> 1, wn = warp & 1;
    const int lr = lane >> 2, lc = lane & 3;
    const int row0 = blockIdx.x * 128;

    #pragma unroll
    for (int i = 0; i < 16; i++) {
        int task = tid + i * 256;
        int arr = task >> 11;
        int r   = (task >> 4) & 127;
        int u   = task & 15;
        int grow = row0 + r;
        uint4 val = make_uint4(0u, 0u, 0u, 0u);
        const __nv_bfloat16* base = arr ? g_hl : g_hh;
        if (grow < M)
            val = *(const uint4*)(base + (size_t)grow * 128 + u * 8);
        *(uint4*)&((arr ? Al : Ah)[r][u * 4]) = val;
    }

    #pragma unroll 1
    for (int w = 0; w < 4; w++) {
        const float* W    = (w == 0) ? Wq : (w == 1) ? Wk : (w == 2) ? Wv : Ws;
        const float* bias = (w == 0) ? bq : (w == 1) ? bk : (w == 2) ? bv : bs;
        float* C          = (w == 0) ? g_q : (w == 1) ? g_k : (w == 2) ? g_v : g_out;

        float acc[2][8][4];
        #pragma unroll
        for (int mt = 0; mt < 2; mt++)
            #pragma unroll
            for (int nt = 0; nt < 8; nt++)
                #pragma unroll
                for (int j = 0; j < 4; j++) acc[mt][nt][j] = 0.f;

        #pragma unroll 1
        for (int k0 = 0; k0 < 128; k0 += 32) {
            #pragma unroll
            for (int i = 0; i < 2; i++) {
                int task = tid + i * 256;
                int kk = task >> 5;
                int n  = (task & 31) * 4;
                int k  = k0 + kk * 2;
                float4 r0 = *(const float4*)(W + (size_t)k * 128 + n);
                float4 r1 = *(const float4*)(W + (size_t)(k + 1) * 128 + n);
                uint4 vh, vl;
                bsplit(r0.x, r1.x, vh.x, vl.x);
                bsplit(r0.y, r1.y, vh.y, vl.y);
                bsplit(r0.z, r1.z, vh.z, vl.z);
                bsplit(r0.w, r1.w, vh.w, vl.w);
                *(uint4*)&Wh[kk][n] = vh;
                *(uint4*)&Wl[kk][n] = vl;
            }
            __syncthreads();

            #pragma unroll
            for (int ks = 0; ks < 2; ks++) {
                const int kbg = (k0 >> 1) + ks * 8;
                const int kb  = ks * 8;
                uint32_t ah[2][4], al[2][4];
                #pragma unroll
                for (int mt = 0; mt < 2; mt++) {
                    int m = wm * 32 + mt * 16 + lr;
                    ah[mt][0] = Ah[m    ][kbg + lc];
                    ah[mt][1] = Ah[m + 8][kbg + lc];
                    ah[mt][2] = Ah[m    ][kbg + lc + 4];
                    ah[mt][3] = Ah[m + 8][kbg + lc + 4];
                    al[mt][0] = Al[m    ][kbg + lc];
                    al[mt][1] = Al[m + 8][kbg + lc];
                    al[mt][2] = Al[m    ][kbg + lc + 4];
                    al[mt][3] = Al[m + 8][kbg + lc + 4];
                }
                #pragma unroll
                for (int nt = 0; nt < 8; nt++) {
                    int n = wn * 64 + nt * 8 + lr;
                    uint32_t bh[2], bl[2];
                    bh[0] = Wh[kb + lc    ][n];
                    bh[1] = Wh[kb + lc + 4][n];
                    bl[0] = Wl[kb + lc    ][n];
                    bl[1] = Wl[kb + lc + 4][n];
                    #pragma unroll
                    for (int mt = 0; mt < 2; mt++) {
                        mma_bf16(acc[mt][nt], ah[mt], bh);
                        mma_bf16(acc[mt][nt], al[mt], bh);
                        mma_bf16(acc[mt][nt], ah[mt], bl);
                    }
                }
            }
            __syncthreads();
        }

        #pragma unroll
        for (int mt = 0; mt < 2; mt++) {
            int rA = row0 + wm * 32 + mt * 16 + lr;
            #pragma unroll
            for (int nt = 0; nt < 8; nt++) {
                int col = wn * 64 + nt * 8 + lc * 2;
                float b0 = bias[col], b1 = bias[col + 1];
                if (rA < M)
                    *(float2*)&C[(size_t)rA * 128 + col] =
                        make_float2(acc[mt][nt][0] + b0, acc[mt][nt][1] + b1);
                if (rA + 8 < M)
                    *(float2*)&C[(size_t)(rA + 8) * 128 + col] =
                        make_float2(acc[mt][nt][2] + b0, acc[mt][nt][3] + b1);
            }
        }
    }
}

// ---------------- We prep ----------------
__global__ void we_split_kernel(const float* __restrict__ We)
{
    int idx = blockIdx.x * blockDim.x + threadIdx.x;
    if (idx >= (TDP/2) * HID) return;
    int p = idx >> 7, n = idx & 127;
    int t0 = 2 * p, t1 = t0 + 1;
    float v0 = (t0 < TD) ? We[t0 * HID + n] : 0.f;
    float v1 = (t1 < TD) ? We[t1 * HID + n] : 0.f;
    uint32_t hi, lo;
    bsplit(v0, v1, hi, lo);
    g_wph[idx] = hi;
    g_wpl[idx] = lo;
}

// ---------------- CSR build (per layer) ----------------
__global__ void zero_deg_kernel(int N)
{
    int i = blockIdx.x * blockDim.x + threadIdx.x;
    if (i < N) g_deg[i] = 0;
}

__global__ void hist_kernel(const int* __restrict__ dst, int E)
{
    int e = blockIdx.x * blockDim.x + threadIdx.x;
    if (e < E) atomicAdd(&g_deg[dst[e]], 1);
}

// single-block two-level exclusive scan over g_deg -> g_start, g_cur
__global__ void scan_kernel(int N)
{
    __shared__ int sh[1024];
    int t = threadIdx.x;
    int chunk = (N + 1023) / 1024;
    int lo = t * chunk;
    int hi = min(N, lo + chunk);
    int sum = 0;
    for (int i = lo; i < hi; i++) sum += g_deg[i];
    sh[t] = sum;
    __syncthreads();
    // inclusive Hillis-Steele
    for (int d = 1; d < 1024; d <<= 1) {
        int v = (t >= d) ? sh[t - d] : 0;
        __syncthreads();
        sh[t] += v;
        __syncthreads();
    }
    int run = sh[t] - sum;   // exclusive prefix of this chunk
    for (int i = lo; i < hi; i++) {
        g_start[i] = run;
        g_cur[i]   = run;
        run += g_deg[i];
    }
}

__global__ void scatter_kernel(const int* __restrict__ dst, int E)
{
    int e = blockIdx.x * blockDim.x + threadIdx.x;
    if (e < E) {
        int pos = atomicAdd(&g_cur[dst[e]], 1);
        g_eidx[pos] = e;
    }
}

// ---------------- edge pass A (tensor-core, register-A, warp-independent) ----------------
// Writes g_e (v[src]+e) and g_a only. No atomics.
#define EA2_WH   0
#define EA2_WL   34816
#define EA2_FR   69632
#define EA2_PH   70144
#define EA2_ES   70656
#define EA2_TOTAL 104448

__global__ void __launch_bounds__(256, 2)
edgeA_mma2(const int* __restrict__ src, const int* __restrict__ dst,
           const float* __restrict__ dt,
           const float* __restrict__ freq, const float* __restrict__ phg, int E)
{
    extern __shared__ char sm[];
    uint32_t (*Wh)[136] = (uint32_t(*)[136])(sm + EA2_WH);
    uint32_t (*Wl)[136] = (uint32_t(*)[136])(sm + EA2_WL);
    float* fr  = (float*)(sm + EA2_FR);
    float* phs = (float*)(sm + EA2_PH);

    const int tid  = threadIdx.x;
    const int warp = tid >> 5, lane = tid & 31;
    const int lr = lane >> 2, lc = lane & 3;
    const long long base = (long long)blockIdx.x * 128;

    float* EsW = (float*)(sm + EA2_ES) + warp * (8 * 132);

    if (tid < 128) {
        fr[tid]  = (tid < TD) ? freq[tid] : 0.f;
        phs[tid] = (tid < TD) ? phg[tid]  : 0.f;
    }
    {
        const uint4* GH = (const uint4*)g_wph;
        const uint4* GL = (const uint4*)g_wpl;
        #pragma unroll
        for (int i = 0; i < 16; i++) {
            int task = tid + i * 256;
            int arr  = task >> 11;
            int rest = task & 2047;
            int p  = rest >> 5;
            int q4 = rest & 31;
            uint4 v = (arr ? GL : GH)[p * 32 + q4];
            *(uint4*)&((arr ? Wl : Wh)[p][q4 * 4]) = v;
        }
    }
    __syncthreads();

    long long eLo = base + warp * 16 + lr;
    long long eHi = eLo + 8;
    float dlo = (eLo < E) ? dt[eLo] : 0.f;
    float dhi = (eHi < E) ? dt[eHi] : 0.f;

    float acc[16][4];
    #pragma unroll
    for (int nt = 0; nt < 16; nt++)
        #pragma unroll
        for (int j = 0; j < 4; j++) acc[nt][j] = 0.f;

    #pragma unroll
    for (int ks = 0; ks < 8; ks++) {
        const int ka = ks * 16 + 2 * lc;
        const int kb2 = ka + 8;
        float f0 = fr[ka],  p0 = phs[ka];
        float f1 = fr[ka+1], p1 = phs[ka+1];
        float f2 = fr[kb2],  p2 = phs[kb2];
        float f3 = fr[kb2+1], p3 = phs[kb2+1];
        float aLo0 = (ka    < TD) ? cosf(fmaf(dlo, f0, p0)) : 0.f;
        float aLo1 = (ka+1  < TD) ? cosf(fmaf(dlo, f1, p1)) : 0.f;
        float aHi0 = (ka    < TD) ? cosf(fmaf(dhi, f0, p0)) : 0.f;
        float aHi1 = (ka+1  < TD) ? cosf(fmaf(dhi, f1, p1)) : 0.f;
        float bLo0 = (kb2   < TD) ? cosf(fmaf(dlo, f2, p2)) : 0.f;
        float bLo1 = (kb2+1 < TD) ? cosf(fmaf(dlo, f3, p3)) : 0.f;
        float bHi0 = (kb2   < TD) ? cosf(fmaf(dhi, f2, p2)) : 0.f;
        float bHi1 = (kb2+1 < TD) ? cosf(fmaf(dhi, f3, p3)) : 0.f;
        uint32_t ah[4], al[4];
        bsplit(aLo0, aLo1, ah[0], al[0]);
        bsplit(aHi0, aHi1, ah[1], al[1]);
        bsplit(bLo0, bLo1, ah[2], al[2]);
        bsplit(bHi0, bHi1, ah[3], al[3]);

        const int kp = ks * 8;
        #pragma unroll
        for (int nt = 0; nt < 16; nt++) {
            int n = nt * 8 + lr;
            uint32_t bh[2], bl[2];
            bh[0] = Wh[kp + lc    ][n];
            bh[1] = Wh[kp + lc + 4][n];
            bl[0] = Wl[kp + lc    ][n];
            bl[1] = Wl[kp + lc + 4][n];
            mma_bf16(acc[nt], ah, bh);
            mma_bf16(acc[nt], al, bh);
            mma_bf16(acc[nt], ah, bl);
        }
    }

    const float inv_sqrt_d = 0.1767766952966369f;
    #pragma unroll
    for (int half = 0; half < 2; half++) {
        #pragma unroll
        for (int nt = 0; nt < 16; nt++) {
            int c0 = nt * 8 + lc * 2;
            *(float2*)&EsW[lr * 132 + c0] =
                make_float2(acc[nt][half * 2 + 0], acc[nt][half * 2 + 1]);
        }
        __syncwarp();
        #pragma unroll
        for (int j = 0; j < 8; j++) {
            long long e = base + warp * 16 + half * 8 + j;
            if (e < E) {
                float4 ev = *(const float4*)&EsW[j * 132 + lane * 4];
                int sI = src[e], dI = dst[e];
                float4 kv = ((const float4*)g_k)[(size_t)sI * 32 + lane];
                float4 qv = ((const float4*)g_q)[(size_t)dI * 32 + lane];
                float4 vv = ((const float4*)g_v)[(size_t)sI * 32 + lane];
                float4 ve;
                ve.x = vv.x + ev.x; ve.y = vv.y + ev.y;
                ve.z = vv.z + ev.z; ve.w = vv.w + ev.w;
                ((float4*)g_e)[(size_t)e * 32 + lane] = ve;
                float p = qv.x*(kv.x+ev.x) + qv.y*(kv.y+ev.y)
                        + qv.z*(kv.z+ev.z) + qv.w*(kv.w+ev.w);
                p += __shfl_xor_sync(0xffffffffu, p, 1);
                p += __shfl_xor_sync(0xffffffffu, p, 2);
                p += __shfl_xor_sync(0xffffffffu, p, 4);
                if ((lane & 7) == 0)
                    g_a[(size_t)e * NH + (lane >> 3)] = expf(p * inv_sqrt_d);
            }
        }
        __syncwarp();
    }
}

// ---------------- node aggregation: warp per node, no atomics ----------------
// out[n] = sum_e a_e * ve_e / sum_e a_e + skip (skip already in g_out)
__global__ void nodeagg_kernel(int N)
{
    int n = (blockIdx.x * blockDim.x + threadIdx.x) >> 5;
    if (n >= N) return;
    int lane = threadIdx.x & 31;
    int head = lane >> 3;
    int start = g_start[n];
    int deg   = g_deg[n];
    float4 acc = make_float4(0.f, 0.f, 0.f, 0.f);
    float s = 0.f;
    for (int i = 0; i < deg; i++) {
        int e = g_eidx[start + i];
        float a = g_a[(size_t)e * NH + head];
        float4 ve = ((const float4*)g_e)[(size_t)e * 32 + lane];
        s += a;
        acc.x += a * ve.x; acc.y += a * ve.y;
        acc.z += a * ve.z; acc.w += a * ve.w;
    }
    float inv = 1.f / (s + 1e-16f);
    float4* op = ((float4*)g_out) + (size_t)n * 32 + lane;
    float4 skip = *op;
    skip.x += acc.x * inv; skip.y += acc.y * inv;
    skip.z += acc.z * inv; skip.w += acc.w * inv;
    *op = skip;
}

// ---------------- utility kernels ----------------
__global__ void zero_kernel(int id, int n)
{
    float* p = bufptr(id);
    for (int i = blockIdx.x * blockDim.x + threadIdx.x; i < n; i += gridDim.x * blockDim.x)
        p[i] = 0.f;
}

__global__ void stats_kernel(int id, int n, int ncols, int prerelu)
{
    const float* X = bufptr(id);
    int c = threadIdx.x;
    float s = 0.f, s2 = 0.f;
    for (int r = blockIdx.x; r < n; r += gridDim.x) {
        float v = X[(size_t)r * ncols + c];
        if (prerelu) v = fmaxf(v, 0.f);
        s += v; s2 += v * v;
    }
    atomicAdd(&g_sums[c], (double)s);
    atomicAdd(&g_sums[128 + c], (double)s2);
}

__global__ void bnfin_kernel(int n, const float* __restrict__ gamma, const float* __restrict__ beta)
{
    int c = threadIdx.x;
    double mean = g_sums[c] / (double)n;
    double var  = g_sums[128 + c] / (double)n - mean * mean;
    float mul = gamma[c] * rsqrtf((float)var + 1e-5f);
    g_bnp[c] = mul;
    g_bnp[128 + c] = beta[c] - (float)mean * mul;
}

__global__ void bn_kernel(int inid, int n, int ncols, int prerelu, int postrelu,
                          int outfId, int outhId, int outlId)
{
    const float* X = bufptr(inid);
    float* Yf = (outfId >= 0) ? bufptr(outfId) : nullptr;
    __nv_bfloat16* Yh = (outhId >= 0) ? bufptr16(outhId) : nullptr;
    __nv_bfloat16* Yl = (outhId >= 0) ? bufptr16(outlId) : nullptr;
    size_t total = (size_t)n * ncols;
    for (size_t i = (size_t)blockIdx.x * blockDim.x + threadIdx.x; i < total;
         i += (size_t)gridDim.x * blockDim.x) {
        int c = (int)(i % ncols);
        float v = X[i];
        if (prerelu) v = fmaxf(v, 0.f);
        float y = v * g_bnp[c] + g_bnp[128 + c];
        if (postrelu) y = fmaxf(y, 0.f);
        if (Yf) Yf[i] = y;
        if (Yh) {
            __nv_bfloat16 h = __float2bfloat16_rn(y);
            Yh[i] = h;
            Yl[i] = __float2bfloat16_rn(y - __bfloat162float(h));
        }
    }
}

__global__ void final_kernel(const float* __restrict__ W3, const float* __restrict__ b3,
                             float* __restrict__ out, int B)
{
    int r = (blockIdx.x * blockDim.x + threadIdx.x) >> 5;
    int lane = threadIdx.x & 31;
    if (r >= B) return;
    const float* z = g_z2 + (size_t)r * 64;
    float acc = z[lane] * W3[lane] + z[lane + 32] * W3[lane + 32];
    acc += __shfl_xor_sync(0xffffffffu, acc, 1);
    acc += __shfl_xor_sync(0xffffffffu, acc, 2);
    acc += __shfl_xor_sync(0xffffffffu, acc, 4);
    acc += __shfl_xor_sync(0xffffffffu, acc, 8);
    acc += __shfl_xor_sync(0xffffffffu, acc, 16);
    if (lane == 0) out[r] = acc + b3[0];
}

// ---------------- host launcher ----------------
extern "C" void kernel_launch(void* const* d_in, const int* in_sizes, int n_in,
                              void* d_out, int out_size)
{
    int off = (n_in >= 31) ? 1 : 0;
    const float* x_all = (const float*)d_in[0];
    const int*   ids   = (const int*)d_in[1];
    const int*   esrc  = (const int*)d_in[2];
    const int*   edst  = (const int*)d_in[3];
    const float* dts   = (const float*)d_in[4];
    const float* basis = (const float*)d_in[5 + off];
    const float* phase = (const float*)d_in[6 + off];
    const float* Wp    = (const float*)d_in[7 + off];
    const float* bp    = (const float*)d_in[8 + off];
    const float* Wq    = (const float*)d_in[9 + off];
    const float* bq    = (const float*)d_in[10 + off];
    const float* Wk    = (const float*)d_in[11 + off];
    const float* bk    = (const float*)d_in[12 + off];
    const float* Wv    = (const float*)d_in[13 + off];
    const float* bv    = (const float*)d_in[14 + off];
    const float* We    = (const float*)d_in[15 + off];
    const float* Wsk   = (const float*)d_in[16 + off];
    const float* bsk   = (const float*)d_in[17 + off];
    const float* bng   = (const float*)d_in[18 + off];
    const float* bnb   = (const float*)d_in[19 + off];
    const float* W1    = (const float*)d_in[20 + off];
    const float* b1    = (const float*)d_in[21 + off];
    const float* g1    = (const float*)d_in[22 + off];
    const float* be1   = (const float*)d_in[23 + off];
    const float* W2    = (const float*)d_in[24 + off];
    const float* b2    = (const float*)d_in[25 + off];
    const float* g2    = (const float*)d_in[26 + off];
    const float* be2   = (const float*)d_in[27 + off];
    const float* W3    = (const float*)d_in[28 + off];
    const float* b3    = (const float*)d_in[29 + off];

    int N = in_sizes[1];
    int E = in_sizes[2] / LNUM;
    int B = out_size;

    int gN = (N + 127) / 128;
    int gB = (B + 127) / 128;

    static int smem_set = 0;
    if (!smem_set) {
        cudaFuncSetAttribute(edgeA_mma2, cudaFuncAttributeMaxDynamicSharedMemorySize, EA2_TOTAL);
        cudaFuncSetAttribute(gemm_qkvs, cudaFuncAttributeMaxDynamicSharedMemorySize, QKVS_TOTAL);
        smem_set = 1;
    }

    // h = relu(x_all[ids] @ Wp + bp)  -> written directly as bf16 hi/lo split
    gemm_tc<128, false><<<gN, 256>>>(x_all, -1, -1, ids, N, IN_DIM, Wp, bp,
                                     -1, 1, ID_HH, ID_HL);

    for (int i = 0; i < LNUM; i++) {
        size_t wo = (size_t)i * HID * HID;
        const int* dsti = edst + (size_t)i * E;

        // CSR build (depends only on dst indices)
        zero_deg_kernel<<<(N + 255) / 256, 256>>>(N);
        hist_kernel<<<(E + 255) / 256, 256>>>(dsti, E);
        scan_kernel<<<1, 1024>>>(N);
        scatter_kernel<<<(E + 255) / 256, 256>>>(dsti, E);

        gemm_qkvs<<<gN, 256, QKVS_TOTAL>>>(N, Wq + wo, Wk + wo, Wv + wo, Wsk + wo,
                                           bq + i*HID, bk + i*HID, bv + i*HID, bsk + i*HID);
        we_split_kernel<<<32, 256>>>(We + (size_t)i * TD * HID);

        edgeA_mma2<<<(E + 127) / 128, 256, EA2_TOTAL>>>(
            esrc + (size_t)i * E, dsti, dts + (size_t)i * E, basis, phase, E);

        nodeagg_kernel<<<(N * 32 + 255) / 256, 256>>>(N);

        zero_kernel<<<4, 256>>>(ID_SUMS, 512);
        stats_kernel<<<512, HID>>>(ID_OUT, N, HID, 1);
        bnfin_kernel<<<1, HID>>>(N, bng + i*HID, bnb + i*HID);
        bn_kernel<<<2048, 256>>>(ID_OUT, N, HID, 1, 0, -1, ID_HH, ID_HL);
    }

    // MLP head on first B rows
    gemm_tc<128, true><<<gB, 256>>>(nullptr, ID_HH, ID_HL, nullptr, B, HID,
                                    W1, b1, ID_Z1, 0, -1, -1);
    zero_kernel<<<4, 256>>>(ID_SUMS, 512);
    stats_kernel<<<512, 128>>>(ID_Z1, B, 128, 0);
    bnfin_kernel<<<1, 128>>>(B, g1, be1);
    bn_kernel<<<1024, 256>>>(ID_Z1, B, 128, 0, 1, -1, ID_Z1H, ID_Z1L);

    gemm_tc<64, true><<<gB, 256>>>(nullptr, ID_Z1H, ID_Z1L, nullptr, B, HID,
                                   W2, b2, ID_Z2, 0, -1, -1);
    zero_kernel<<<4, 256>>>(ID_SUMS, 512);
    stats_kernel<<<512, 64>>>(ID_Z2, B, 64, 0);
    bnfin_kernel<<<1, 64>>>(B, g2, be2);
    bn_kernel<<<1024, 256>>>(ID_Z2, B, 64, 0, 1, ID_Z2, -1, -1);

    final_kernel<<<(B * 32 + 255) / 256, 256>>>(W3, b3, (float*)d_out, B);
}

// round 13
// speedup vs baseline: 1.2391x; 1.2391x over previous
#include <cuda_runtime.h>
#include <cuda_bf16.h>
#include <math.h>
#include <stdint.h>

#define LNUM 2
#define IN_DIM 172
#define HID 128
#define NH 4
#define HD 32
#define TD 100
#define TDP 128
#define NMAX 150016
#define EMAX 500224
#define BMAX 16384
#define SCAN_BLK 1024
#define SCAN_MAXB 256

#define ID_Q    1
#define ID_K    2
#define ID_V    3
#define ID_OUT  4
#define ID_Z1   5
#define ID_Z2   6
#define ID_SUMS 8
#define ID_HH   9
#define ID_HL   10
#define ID_Z1H  11
#define ID_Z1L  12

// ---------------- scratch (static device memory; no cudaMalloc allowed) ----------------
__device__ float  g_q  [(size_t)NMAX * HID];
__device__ float  g_k  [(size_t)NMAX * HID];
__device__ float  g_v  [(size_t)NMAX * HID];
__device__ float  g_out[(size_t)NMAX * HID];
__device__ float  g_e  [(size_t)EMAX * HID];   // v[src] + e  per edge
__device__ float  g_a  [(size_t)EMAX * NH];
__device__ float  g_z1 [(size_t)BMAX * HID];
__device__ float  g_z2 [(size_t)BMAX * (HID/2)];
__device__ __nv_bfloat16 g_hh [(size_t)NMAX * HID];
__device__ __nv_bfloat16 g_hl [(size_t)NMAX * HID];
__device__ __nv_bfloat16 g_z1h[(size_t)BMAX * HID];
__device__ __nv_bfloat16 g_z1l[(size_t)BMAX * HID];
__device__ __align__(16) uint32_t g_wph[(TDP/2) * HID];
__device__ __align__(16) uint32_t g_wpl[(TDP/2) * HID];
__device__ int    g_deg  [NMAX];
__device__ int    g_start[NMAX];
__device__ int    g_cur  [NMAX];
__device__ int    g_eidx [EMAX];
__device__ int    g_bsum [SCAN_MAXB];
__device__ int    g_boff [SCAN_MAXB];
__device__ double g_sums[256];
__device__ float  g_bnp[256];

__device__ __forceinline__ float* bufptr(int id) {
    switch (id) {
        case ID_Q:    return g_q;
        case ID_K:    return g_k;
        case ID_V:    return g_v;
        case ID_OUT:  return g_out;
        case ID_Z1:   return g_z1;
        case ID_Z2:   return g_z2;
        case ID_SUMS: return (float*)g_sums;
    }
    return nullptr;
}

__device__ __forceinline__ __nv_bfloat16* bufptr16(int id) {
    switch (id) {
        case ID_HH:  return g_hh;
        case ID_HL:  return g_hl;
        case ID_Z1H: return g_z1h;
        case ID_Z1L: return g_z1l;
    }
    return nullptr;
}

// ---------------- bf16 hi/lo split helpers ----------------
__device__ __forceinline__ void bsplit(float x, float y, uint32_t& hi, uint32_t& lo) {
    __nv_bfloat162 h;
    h.x = __float2bfloat16_rn(x);
    h.y = __float2bfloat16_rn(y);
    hi = *reinterpret_cast<uint32_t*>(&h);
    __nv_bfloat162 l;
    l.x = __float2bfloat16_rn(x - __bfloat162float(h.x));
    l.y = __float2bfloat16_rn(y - __bfloat162float(h.y));
    lo = *reinterpret_cast<uint32_t*>(&l);
}

__device__ __forceinline__ void mma_bf16(float* c, const uint32_t* a, const uint32_t* b) {
    asm volatile(
        "mma.sync.aligned.m16n8k16.row.col.f32.bf16.bf16.f32 "
        "{%0,%1,%2,%3}, {%4,%5,%6,%7}, {%8,%9}, {%0,%1,%2,%3};\n"
        : "+f"(c[0]), "+f"(c[1]), "+f"(c[2]), "+f"(c[3])
        : "r"(a[0]), "r"(a[1]), "r"(a[2]), "r"(a[3]), "r"(b[0]), "r"(b[1]));
}

// ---------------- generic tensor-core GEMM (gather GEMM, W1, W2) ----------------
template <int NC, bool PRESPLIT>
__global__ void __launch_bounds__(256, 2)
gemm_tc(const float* __restrict__ Aext, int AhId, int AlId, const int* __restrict__ gather,
        int M, int K, const float* __restrict__ W, const float* __restrict__ bias,
        int Cid, int relu, int ChId, int ClId)
{
    constexpr int BM = 128, BK = 32, K2 = 16;
    constexpr int AP = 20;
    constexpr int WP = NC + 8;
    constexpr int WN = NC / 2;
    constexpr int NT = WN / 8;
    constexpr int MT = 2;

    __shared__ uint32_t Ah[BM][AP], Al[BM][AP];
    __shared__ uint32_t Wh[K2][WP], Wl[K2][WP];

    const int tid  = threadIdx.x;
    const int warp = tid >> 5, lane = tid & 31;
    const int wm = warp >> 1, wn = warp & 1;
    const int lr = lane >> 2, lc = lane & 3;
    const int row0 = blockIdx.x * BM;

    float acc[MT][NT][4];
    #pragma unroll
    for (int mt = 0; mt < MT; mt++)
        #pragma unroll
        for (int nt = 0; nt < NT; nt++)
            #pragma unroll
            for (int j = 0; j < 4; j++) acc[mt][nt][j] = 0.f;

    for (int k0 = 0; k0 < K; k0 += BK) {
        if (PRESPLIT) {
            const __nv_bfloat16* AH = bufptr16(AhId);
            const __nv_bfloat16* AL = bufptr16(AlId);
            #pragma unroll
            for (int i = 0; i < 4; i++) {
                int task = tid + i * 256;
                int arr = task >> 9;
                int r   = (task >> 2) & 127;
                int u   = task & 3;
                int grow = row0 + r;
                uint4 val = make_uint4(0u, 0u, 0u, 0u);
                const __nv_bfloat16* base = arr ? AL : AH;
                if (grow < M)
                    val = *(const uint4*)(base + (size_t)grow * K + k0 + u * 8);
                *(uint4*)&((arr ? Al : Ah)[r][u * 4]) = val;
            }
        } else {
            #pragma unroll
            for (int i = 0; i < 4; i++) {
                int task = tid + i * 256;
                int r  = task >> 3;
                int kg = task & 7;
                int k  = k0 + kg * 4;
                float4 v = make_float4(0.f, 0.f, 0.f, 0.f);
                int grow = row0 + r;
                if (grow < M) {
                    long long ar = gather ? (long long)gather[grow] : (long long)grow;
                    const float* ap = Aext + ar * K + k;
                    if (k + 4 <= K) v = *(const float4*)ap;
                    else {
                        if (k     < K) v.x = ap[0];
                        if (k + 1 < K) v.y = ap[1];
                        if (k + 2 < K) v.z = ap[2];
                        if (k + 3 < K) v.w = ap[3];
                    }
                }
                uint32_t h0, l0, h1, l1;
                bsplit(v.x, v.y, h0, l0);
                bsplit(v.z, v.w, h1, l1);
                *(uint2*)&Ah[r][kg * 2] = make_uint2(h0, h1);
                *(uint2*)&Al[r][kg * 2] = make_uint2(l0, l1);
            }
        }
        #pragma unroll
        for (int i = 0; i < (K2 * NC / 4) / 256; i++) {
            int task = tid + i * 256;
            int kk = task / (NC / 4);
            int n  = (task % (NC / 4)) * 4;
            int k  = k0 + kk * 2;
            float4 r0 = make_float4(0.f,0.f,0.f,0.f), r1 = make_float4(0.f,0.f,0.f,0.f);
            if (k     < K) r0 = *(const float4*)(W + (size_t)k * NC + n);
            if (k + 1 < K) r1 = *(const float4*)(W + (size_t)(k + 1) * NC + n);
            uint4 vh, vl;
            bsplit(r0.x, r1.x, vh.x, vl.x);
            bsplit(r0.y, r1.y, vh.y, vl.y);
            bsplit(r0.z, r1.z, vh.z, vl.z);
            bsplit(r0.w, r1.w, vh.w, vl.w);
            *(uint4*)&Wh[kk][n] = vh;
            *(uint4*)&Wl[kk][n] = vl;
        }
        __syncthreads();

        #pragma unroll
        for (int ks = 0; ks < 2; ks++) {
            const int kb = ks * 8;
            uint32_t ah[MT][4], al[MT][4];
            #pragma unroll
            for (int mt = 0; mt < MT; mt++) {
                int m = wm * 32 + mt * 16 + lr;
                ah[mt][0] = Ah[m    ][kb + lc];
                ah[mt][1] = Ah[m + 8][kb + lc];
                ah[mt][2] = Ah[m    ][kb + lc + 4];
                ah[mt][3] = Ah[m + 8][kb + lc + 4];
                al[mt][0] = Al[m    ][kb + lc];
                al[mt][1] = Al[m + 8][kb + lc];
                al[mt][2] = Al[m    ][kb + lc + 4];
                al[mt][3] = Al[m + 8][kb + lc + 4];
            }
            #pragma unroll
            for (int nt = 0; nt < NT; nt++) {
                int n = wn * WN + nt * 8 + lr;
                uint32_t bh[2], bl[2];
                bh[0] = Wh[kb + lc    ][n];
                bh[1] = Wh[kb + lc + 4][n];
                bl[0] = Wl[kb + lc    ][n];
                bl[1] = Wl[kb + lc + 4][n];
                #pragma unroll
                for (int mt = 0; mt < MT; mt++) {
                    mma_bf16(acc[mt][nt], ah[mt], bh);
                    mma_bf16(acc[mt][nt], al[mt], bh);
                    mma_bf16(acc[mt][nt], ah[mt], bl);
                }
            }
        }
        __syncthreads();
    }

    float* C = (Cid >= 0) ? bufptr(Cid) : nullptr;
    __nv_bfloat16* CH = (ChId >= 0) ? bufptr16(ChId) : nullptr;
    __nv_bfloat16* CL = (ChId >= 0) ? bufptr16(ClId) : nullptr;
    #pragma unroll
    for (int mt = 0; mt < MT; mt++) {
        int rA = row0 + wm * 32 + mt * 16 + lr;
        #pragma unroll
        for (int nt = 0; nt < NT; nt++) {
            int col = wn * WN + nt * 8 + lc * 2;
            float b0 = bias[col], b1 = bias[col + 1];
            float2 v0 = make_float2(acc[mt][nt][0] + b0, acc[mt][nt][1] + b1);
            float2 v1 = make_float2(acc[mt][nt][2] + b0, acc[mt][nt][3] + b1);
            if (relu) {
                v0.x = fmaxf(v0.x, 0.f); v0.y = fmaxf(v0.y, 0.f);
                v1.x = fmaxf(v1.x, 0.f); v1.y = fmaxf(v1.y, 0.f);
            }
            #pragma unroll
            for (int half = 0; half < 2; half++) {
                int r = rA + half * 8;
                if (r >= M) continue;
                float2 v = half ? v1 : v0;
                size_t idx = (size_t)r * NC + col;
                if (C) *(float2*)&C[idx] = v;
                if (CH) {
                    __nv_bfloat16 h0 = __float2bfloat16_rn(v.x);
                    __nv_bfloat16 h1 = __float2bfloat16_rn(v.y);
                    CH[idx]     = h0;
                    CH[idx + 1] = h1;
                    CL[idx]     = __float2bfloat16_rn(v.x - __bfloat162float(h0));
                    CL[idx + 1] = __float2bfloat16_rn(v.y - __bfloat162float(h1));
                }
            }
        }
    }
}

// ---------------- fused Q/K/V/skip GEMM: A (K=128) loaded to smem ONCE ----------------
#define QKVS_A1   34816
#define QKVS_W0   69632
#define QKVS_W1B  (QKVS_W0 + 16*136*4)
#define QKVS_TOTAL (QKVS_W1B + 16*136*4)

__global__ void __launch_bounds__(256, 2)
gemm_qkvs(int M,
          const float* __restrict__ Wq, const float* __restrict__ Wk,
          const float* __restrict__ Wv, const float* __restrict__ Ws,
          const float* __restrict__ bq, const float* __restrict__ bk,
          const float* __restrict__ bv, const float* __restrict__ bs)
{
    extern __shared__ char sm[];
    uint32_t (*Ah)[68]  = (uint32_t(*)[68])sm;
    uint32_t (*Al)[68]  = (uint32_t(*)[68])(sm + QKVS_A1);
    uint32_t (*Wh)[136] = (uint32_t(*)[136])(sm + QKVS_W0);
    uint32_t (*Wl)[136] = (uint32_t(*)[136])(sm + QKVS_W1B);

    const int tid  = threadIdx.x;
    const int warp = tid >> 5, lane = tid & 31;
    const int wm = warp >> 1, wn = warp & 1;
    const int lr = lane >> 2, lc = lane & 3;
    const int row0 = blockIdx.x * 128;

    #pragma unroll
    for (int i = 0; i < 16; i++) {
        int task = tid + i * 256;
        int arr = task >> 11;
        int r   = (task >> 4) & 127;
        int u   = task & 15;
        int grow = row0 + r;
        uint4 val = make_uint4(0u, 0u, 0u, 0u);
        const __nv_bfloat16* base = arr ? g_hl : g_hh;
        if (grow < M)
            val = *(const uint4*)(base + (size_t)grow * 128 + u * 8);
        *(uint4*)&((arr ? Al : Ah)[r][u * 4]) = val;
    }

    #pragma unroll 1
    for (int w = 0; w < 4; w++) {
        const float* W    = (w == 0) ? Wq : (w == 1) ? Wk : (w == 2) ? Wv : Ws;
        const float* bias = (w == 0) ? bq : (w == 1) ? bk : (w == 2) ? bv : bs;
        float* C          = (w == 0) ? g_q : (w == 1) ? g_k : (w == 2) ? g_v : g_out;

        float acc[2][8][4];
        #pragma unroll
        for (int mt = 0; mt < 2; mt++)
            #pragma unroll
            for (int nt = 0; nt < 8; nt++)
                #pragma unroll
                for (int j = 0; j < 4; j++) acc[mt][nt][j] = 0.f;

        #pragma unroll 1
        for (int k0 = 0; k0 < 128; k0 += 32) {
            #pragma unroll
            for (int i = 0; i < 2; i++) {
                int task = tid + i * 256;
                int kk = task >> 5;
                int n  = (task & 31) * 4;
                int k  = k0 + kk * 2;
                float4 r0 = *(const float4*)(W + (size_t)k * 128 + n);
                float4 r1 = *(const float4*)(W + (size_t)(k + 1) * 128 + n);
                uint4 vh, vl;
                bsplit(r0.x, r1.x, vh.x, vl.x);
                bsplit(r0.y, r1.y, vh.y, vl.y);
                bsplit(r0.z, r1.z, vh.z, vl.z);
                bsplit(r0.w, r1.w, vh.w, vl.w);
                *(uint4*)&Wh[kk][n] = vh;
                *(uint4*)&Wl[kk][n] = vl;
            }
            __syncthreads();

            #pragma unroll
            for (int ks = 0; ks < 2; ks++) {
                const int kbg = (k0 >> 1) + ks * 8;
                const int kb  = ks * 8;
                uint32_t ah[2][4], al[2][4];
                #pragma unroll
                for (int mt = 0; mt < 2; mt++) {
                    int m = wm * 32 + mt * 16 + lr;
                    ah[mt][0] = Ah[m    ][kbg + lc];
                    ah[mt][1] = Ah[m + 8][kbg + lc];
                    ah[mt][2] = Ah[m    ][kbg + lc + 4];
                    ah[mt][3] = Ah[m + 8][kbg + lc + 4];
                    al[mt][0] = Al[m    ][kbg + lc];
                    al[mt][1] = Al[m + 8][kbg + lc];
                    al[mt][2] = Al[m    ][kbg + lc + 4];
                    al[mt][3] = Al[m + 8][kbg + lc + 4];
                }
                #pragma unroll
                for (int nt = 0; nt < 8; nt++) {
                    int n = wn * 64 + nt * 8 + lr;
                    uint32_t bh[2], bl[2];
                    bh[0] = Wh[kb + lc    ][n];
                    bh[1] = Wh[kb + lc + 4][n];
                    bl[0] = Wl[kb + lc    ][n];
                    bl[1] = Wl[kb + lc + 4][n];
                    #pragma unroll
                    for (int mt = 0; mt < 2; mt++) {
                        mma_bf16(acc[mt][nt], ah[mt], bh);
                        mma_bf16(acc[mt][nt], al[mt], bh);
                        mma_bf16(acc[mt][nt], ah[mt], bl);
                    }
                }
            }
            __syncthreads();
        }

        #pragma unroll
        for (int mt = 0; mt < 2; mt++) {
            int rA = row0 + wm * 32 + mt * 16 + lr;
            #pragma unroll
            for (int nt = 0; nt < 8; nt++) {
                int col = wn * 64 + nt * 8 + lc * 2;
                float b0 = bias[col], b1 = bias[col + 1];
                if (rA < M)
                    *(float2*)&C[(size_t)rA * 128 + col] =
                        make_float2(acc[mt][nt][0] + b0, acc[mt][nt][1] + b1);
                if (rA + 8 < M)
                    *(float2*)&C[(size_t)(rA + 8) * 128 + col] =
                        make_float2(acc[mt][nt][2] + b0, acc[mt][nt][3] + b1);
            }
        }
    }
}

// ---------------- We prep ----------------
__global__ void we_split_kernel(const float* __restrict__ We)
{
    int idx = blockIdx.x * blockDim.x + threadIdx.x;
    if (idx >= (TDP/2) * HID) return;
    int p = idx >> 7, n = idx & 127;
    int t0 = 2 * p, t1 = t0 + 1;
    float v0 = (t0 < TD) ? We[t0 * HID + n] : 0.f;
    float v1 = (t1 < TD) ? We[t1 * HID + n] : 0.f;
    uint32_t hi, lo;
    bsplit(v0, v1, hi, lo);
    g_wph[idx] = hi;
    g_wpl[idx] = lo;
}

// ---------------- CSR build (per layer) ----------------
__global__ void zero_deg_kernel(int N)
{
    int i = blockIdx.x * blockDim.x + threadIdx.x;
    if (i < N) g_deg[i] = 0;
}

__global__ void hist_kernel(const int* __restrict__ dst, int E)
{
    int e = blockIdx.x * blockDim.x + threadIdx.x;
    if (e < E) atomicAdd(&g_deg[dst[e]], 1);
}

// scanA: per-block exclusive scan of a 1024-element chunk; block total -> g_bsum
__global__ void scanA_kernel(int N)
{
    __shared__ int sh[SCAN_BLK];
    int t = threadIdx.x;
    int i = blockIdx.x * SCAN_BLK + t;
    int v = (i < N) ? g_deg[i] : 0;
    sh[t] = v;
    __syncthreads();
    #pragma unroll
    for (int d = 1; d < SCAN_BLK; d <<= 1) {
        int u = (t >= d) ? sh[t - d] : 0;
        __syncthreads();
        sh[t] += u;
        __syncthreads();
    }
    if (i < N) g_start[i] = sh[t] - v;       // local exclusive prefix
    if (t == SCAN_BLK - 1) g_bsum[blockIdx.x] = sh[t];
}

// scanB: single block scans block totals -> exclusive offsets
__global__ void scanB_kernel(int nb)
{
    __shared__ int sh[SCAN_MAXB];
    int t = threadIdx.x;
    int v = (t < nb) ? g_bsum[t] : 0;
    sh[t] = v;
    __syncthreads();
    #pragma unroll
    for (int d = 1; d < SCAN_MAXB; d <<= 1) {
        int u = (t >= d) ? sh[t - d] : 0;
        __syncthreads();
        sh[t] += u;
        __syncthreads();
    }
    if (t < nb) g_boff[t] = sh[t] - v;
}

// scanC: add block offsets, init g_cur
__global__ void scanC_kernel(int N)
{
    int i = blockIdx.x * blockDim.x + threadIdx.x;
    if (i < N) {
        int s = g_start[i] + g_boff[i >> 10];
        g_start[i] = s;
        g_cur[i]   = s;
    }
}

__global__ void scatter_kernel(const int* __restrict__ dst, int E)
{
    int e = blockIdx.x * blockDim.x + threadIdx.x;
    if (e < E) {
        int pos = atomicAdd(&g_cur[dst[e]], 1);
        g_eidx[pos] = e;
    }
}

// ---------------- edge pass A (tensor-core, register-A, warp-independent) ----------------
#define EA2_WH   0
#define EA2_WL   34816
#define EA2_FR   69632
#define EA2_PH   70144
#define EA2_ES   70656
#define EA2_TOTAL 104448

__global__ void __launch_bounds__(256, 2)
edgeA_mma2(const int* __restrict__ src, const int* __restrict__ dst,
           const float* __restrict__ dt,
           const float* __restrict__ freq, const float* __restrict__ phg, int E)
{
    extern __shared__ char sm[];
    uint32_t (*Wh)[136] = (uint32_t(*)[136])(sm + EA2_WH);
    uint32_t (*Wl)[136] = (uint32_t(*)[136])(sm + EA2_WL);
    float* fr  = (float*)(sm + EA2_FR);
    float* phs = (float*)(sm + EA2_PH);

    const int tid  = threadIdx.x;
    const int warp = tid >> 5, lane = tid & 31;
    const int lr = lane >> 2, lc = lane & 3;
    const long long base = (long long)blockIdx.x * 128;

    float* EsW = (float*)(sm + EA2_ES) + warp * (8 * 132);

    if (tid < 128) {
        fr[tid]  = (tid < TD) ? freq[tid] : 0.f;
        phs[tid] = (tid < TD) ? phg[tid]  : 0.f;
    }
    {
        const uint4* GH = (const uint4*)g_wph;
        const uint4* GL = (const uint4*)g_wpl;
        #pragma unroll
        for (int i = 0; i < 16; i++) {
            int task = tid + i * 256;
            int arr  = task >> 11;
            int rest = task & 2047;
            int p  = rest >> 5;
            int q4 = rest & 31;
            uint4 v = (arr ? GL : GH)[p * 32 + q4];
            *(uint4*)&((arr ? Wl : Wh)[p][q4 * 4]) = v;
        }
    }
    __syncthreads();

    long long eLo = base + warp * 16 + lr;
    long long eHi = eLo + 8;
    float dlo = (eLo < E) ? dt[eLo] : 0.f;
    float dhi = (eHi < E) ? dt[eHi] : 0.f;

    float acc[16][4];
    #pragma unroll
    for (int nt = 0; nt < 16; nt++)
        #pragma unroll
        for (int j = 0; j < 4; j++) acc[nt][j] = 0.f;

    #pragma unroll
    for (int ks = 0; ks < 8; ks++) {
        const int ka = ks * 16 + 2 * lc;
        const int kb2 = ka + 8;
        float f0 = fr[ka],  p0 = phs[ka];
        float f1 = fr[ka+1], p1 = phs[ka+1];
        float f2 = fr[kb2],  p2 = phs[kb2];
        float f3 = fr[kb2+1], p3 = phs[kb2+1];
        float aLo0 = (ka    < TD) ? cosf(fmaf(dlo, f0, p0)) : 0.f;
        float aLo1 = (ka+1  < TD) ? cosf(fmaf(dlo, f1, p1)) : 0.f;
        float aHi0 = (ka    < TD) ? cosf(fmaf(dhi, f0, p0)) : 0.f;
        float aHi1 = (ka+1  < TD) ? cosf(fmaf(dhi, f1, p1)) : 0.f;
        float bLo0 = (kb2   < TD) ? cosf(fmaf(dlo, f2, p2)) : 0.f;
        float bLo1 = (kb2+1 < TD) ? cosf(fmaf(dlo, f3, p3)) : 0.f;
        float bHi0 = (kb2   < TD) ? cosf(fmaf(dhi, f2, p2)) : 0.f;
        float bHi1 = (kb2+1 < TD) ? cosf(fmaf(dhi, f3, p3)) : 0.f;
        uint32_t ah[4], al[4];
        bsplit(aLo0, aLo1, ah[0], al[0]);
        bsplit(aHi0, aHi1, ah[1], al[1]);
        bsplit(bLo0, bLo1, ah[2], al[2]);
        bsplit(bHi0, bHi1, ah[3], al[3]);

        const int kp = ks * 8;
        #pragma unroll
        for (int nt = 0; nt < 16; nt++) {
            int n = nt * 8 + lr;
            uint32_t bh[2], bl[2];
            bh[0] = Wh[kp + lc    ][n];
            bh[1] = Wh[kp + lc + 4][n];
            bl[0] = Wl[kp + lc    ][n];
            bl[1] = Wl[kp + lc + 4][n];
            mma_bf16(acc[nt], ah, bh);
            mma_bf16(acc[nt], al, bh);
            mma_bf16(acc[nt], ah, bl);
        }
    }

    const float inv_sqrt_d = 0.1767766952966369f;
    #pragma unroll
    for (int half = 0; half < 2; half++) {
        #pragma unroll
        for (int nt = 0; nt < 16; nt++) {
            int c0 = nt * 8 + lc * 2;
            *(float2*)&EsW[lr * 132 + c0] =
                make_float2(acc[nt][half * 2 + 0], acc[nt][half * 2 + 1]);
        }
        __syncwarp();
        #pragma unroll
        for (int j = 0; j < 8; j++) {
            long long e = base + warp * 16 + half * 8 + j;
            if (e < E) {
                float4 ev = *(const float4*)&EsW[j * 132 + lane * 4];
                int sI = src[e], dI = dst[e];
                float4 kv = ((const float4*)g_k)[(size_t)sI * 32 + lane];
                float4 qv = ((const float4*)g_q)[(size_t)dI * 32 + lane];
                float4 vv = ((const float4*)g_v)[(size_t)sI * 32 + lane];
                float4 ve;
                ve.x = vv.x + ev.x; ve.y = vv.y + ev.y;
                ve.z = vv.z + ev.z; ve.w = vv.w + ev.w;
                ((float4*)g_e)[(size_t)e * 32 + lane] = ve;
                float p = qv.x*(kv.x+ev.x) + qv.y*(kv.y+ev.y)
                        + qv.z*(kv.z+ev.z) + qv.w*(kv.w+ev.w);
                p += __shfl_xor_sync(0xffffffffu, p, 1);
                p += __shfl_xor_sync(0xffffffffu, p, 2);
                p += __shfl_xor_sync(0xffffffffu, p, 4);
                if ((lane & 7) == 0)
                    g_a[(size_t)e * NH + (lane >> 3)] = expf(p * inv_sqrt_d);
            }
        }
        __syncwarp();
    }
}

// ---------------- node aggregation: warp per node, no atomics ----------------
__global__ void nodeagg_kernel(int N)
{
    int n = (blockIdx.x * blockDim.x + threadIdx.x) >> 5;
    if (n >= N) return;
    int lane = threadIdx.x & 31;
    int head = lane >> 3;
    int start = g_start[n];
    int deg   = g_deg[n];
    float4 acc = make_float4(0.f, 0.f, 0.f, 0.f);
    float s = 0.f;
    for (int i = 0; i < deg; i++) {
        int e = g_eidx[start + i];
        float a = g_a[(size_t)e * NH + head];
        float4 ve = ((const float4*)g_e)[(size_t)e * 32 + lane];
        s += a;
        acc.x += a * ve.x; acc.y += a * ve.y;
        acc.z += a * ve.z; acc.w += a * ve.w;
    }
    float inv = 1.f / (s + 1e-16f);
    float4* op = ((float4*)g_out) + (size_t)n * 32 + lane;
    float4 skip = *op;
    skip.x += acc.x * inv; skip.y += acc.y * inv;
    skip.z += acc.z * inv; skip.w += acc.w * inv;
    *op = skip;
}

// ---------------- utility kernels ----------------
__global__ void zero_kernel(int id, int n)
{
    float* p = bufptr(id);
    for (int i = blockIdx.x * blockDim.x + threadIdx.x; i < n; i += gridDim.x * blockDim.x)
        p[i] = 0.f;
}

__global__ void stats_kernel(int id, int n, int ncols, int prerelu)
{
    const float* X = bufptr(id);
    int c = threadIdx.x;
    float s = 0.f, s2 = 0.f;
    for (int r = blockIdx.x; r < n; r += gridDim.x) {
        float v = X[(size_t)r * ncols + c];
        if (prerelu) v = fmaxf(v, 0.f);
        s += v; s2 += v * v;
    }
    atomicAdd(&g_sums[c], (double)s);
    atomicAdd(&g_sums[128 + c], (double)s2);
}

__global__ void bnfin_kernel(int n, const float* __restrict__ gamma, const float* __restrict__ beta)
{
    int c = threadIdx.x;
    double mean = g_sums[c] / (double)n;
    double var  = g_sums[128 + c] / (double)n - mean * mean;
    float mul = gamma[c] * rsqrtf((float)var + 1e-5f);
    g_bnp[c] = mul;
    g_bnp[128 + c] = beta[c] - (float)mean * mul;
}

__global__ void bn_kernel(int inid, int n, int ncols, int prerelu, int postrelu,
                          int outfId, int outhId, int outlId)
{
    const float* X = bufptr(inid);
    float* Yf = (outfId >= 0) ? bufptr(outfId) : nullptr;
    __nv_bfloat16* Yh = (outhId >= 0) ? bufptr16(outhId) : nullptr;
    __nv_bfloat16* Yl = (outhId >= 0) ? bufptr16(outlId) : nullptr;
    size_t total = (size_t)n * ncols;
    for (size_t i = (size_t)blockIdx.x * blockDim.x + threadIdx.x; i < total;
         i += (size_t)gridDim.x * blockDim.x) {
        int c = (int)(i % ncols);
        float v = X[i];
        if (prerelu) v = fmaxf(v, 0.f);
        float y = v * g_bnp[c] + g_bnp[128 + c];
        if (postrelu) y = fmaxf(y, 0.f);
        if (Yf) Yf[i] = y;
        if (Yh) {
            __nv_bfloat16 h = __float2bfloat16_rn(y);
            Yh[i] = h;
            Yl[i] = __float2bfloat16_rn(y - __bfloat162float(h));
        }
    }
}

__global__ void final_kernel(const float* __restrict__ W3, const float* __restrict__ b3,
                             float* __restrict__ out, int B)
{
    int r = (blockIdx.x * blockDim.x + threadIdx.x) >> 5;
    int lane = threadIdx.x & 31;
    if (r >= B) return;
    const float* z = g_z2 + (size_t)r * 64;
    float acc = z[lane] * W3[lane] + z[lane + 32] * W3[lane + 32];
    acc += __shfl_xor_sync(0xffffffffu, acc, 1);
    acc += __shfl_xor_sync(0xffffffffu, acc, 2);
    acc += __shfl_xor_sync(0xffffffffu, acc, 4);
    acc += __shfl_xor_sync(0xffffffffu, acc, 8);
    acc += __shfl_xor_sync(0xffffffffu, acc, 16);
    if (lane == 0) out[r] = acc + b3[0];
}

// ---------------- host launcher ----------------
extern "C" void kernel_launch(void* const* d_in, const int* in_sizes, int n_in,
                              void* d_out, int out_size)
{
    int off = (n_in >= 31) ? 1 : 0;
    const float* x_all = (const float*)d_in[0];
    const int*   ids   = (const int*)d_in[1];
    const int*   esrc  = (const int*)d_in[2];
    const int*   edst  = (const int*)d_in[3];
    const float* dts   = (const float*)d_in[4];
    const float* basis = (const float*)d_in[5 + off];
    const float* phase = (const float*)d_in[6 + off];
    const float* Wp    = (const float*)d_in[7 + off];
    const float* bp    = (const float*)d_in[8 + off];
    const float* Wq    = (const float*)d_in[9 + off];
    const float* bq    = (const float*)d_in[10 + off];
    const float* Wk    = (const float*)d_in[11 + off];
    const float* bk    = (const float*)d_in[12 + off];
    const float* Wv    = (const float*)d_in[13 + off];
    const float* bv    = (const float*)d_in[14 + off];
    const float* We    = (const float*)d_in[15 + off];
    const float* Wsk   = (const float*)d_in[16 + off];
    const float* bsk   = (const float*)d_in[17 + off];
    const float* bng   = (const float*)d_in[18 + off];
    const float* bnb   = (const float*)d_in[19 + off];
    const float* W1    = (const float*)d_in[20 + off];
    const float* b1    = (const float*)d_in[21 + off];
    const float* g1    = (const float*)d_in[22 + off];
    const float* be1   = (const float*)d_in[23 + off];
    const float* W2    = (const float*)d_in[24 + off];
    const float* b2    = (const float*)d_in[25 + off];
    const float* g2    = (const float*)d_in[26 + off];
    const float* be2   = (const float*)d_in[27 + off];
    const float* W3    = (const float*)d_in[28 + off];
    const float* b3    = (const float*)d_in[29 + off];

    int N = in_sizes[1];
    int E = in_sizes[2] / LNUM;
    int B = out_size;

    int gN = (N + 127) / 128;
    int gB = (B + 127) / 128;
    int nb = (N + SCAN_BLK - 1) / SCAN_BLK;

    static int smem_set = 0;
    if (!smem_set) {
        cudaFuncSetAttribute(edgeA_mma2, cudaFuncAttributeMaxDynamicSharedMemorySize, EA2_TOTAL);
        cudaFuncSetAttribute(gemm_qkvs, cudaFuncAttributeMaxDynamicSharedMemorySize, QKVS_TOTAL);
        smem_set = 1;
    }

    // h = relu(x_all[ids] @ Wp + bp)  -> written directly as bf16 hi/lo split
    gemm_tc<128, false><<<gN, 256>>>(x_all, -1, -1, ids, N, IN_DIM, Wp, bp,
                                     -1, 1, ID_HH, ID_HL);

    for (int i = 0; i < LNUM; i++) {
        size_t wo = (size_t)i * HID * HID;
        const int* dsti = edst + (size_t)i * E;

        // CSR build (multi-block scan)
        zero_deg_kernel<<<(N + 255) / 256, 256>>>(N);
        hist_kernel<<<(E + 255) / 256, 256>>>(dsti, E);
        scanA_kernel<<<nb, SCAN_BLK>>>(N);
        scanB_kernel<<<1, SCAN_MAXB>>>(nb);
        scanC_kernel<<<(N + 255) / 256, 256>>>(N);
        scatter_kernel<<<(E + 255) / 256, 256>>>(dsti, E);

        gemm_qkvs<<<gN, 256, QKVS_TOTAL>>>(N, Wq + wo, Wk + wo, Wv + wo, Wsk + wo,
                                           bq + i*HID, bk + i*HID, bv + i*HID, bsk + i*HID);
        we_split_kernel<<<32, 256>>>(We + (size_t)i * TD * HID);

        edgeA_mma2<<<(E + 127) / 128, 256, EA2_TOTAL>>>(
            esrc + (size_t)i * E, dsti, dts + (size_t)i * E, basis, phase, E);

        nodeagg_kernel<<<(N * 32 + 255) / 256, 256>>>(N);

        zero_kernel<<<4, 256>>>(ID_SUMS, 512);
        stats_kernel<<<512, HID>>>(ID_OUT, N, HID, 1);
        bnfin_kernel<<<1, HID>>>(N, bng + i*HID, bnb + i*HID);
        bn_kernel<<<2048, 256>>>(ID_OUT, N, HID, 1, 0, -1, ID_HH, ID_HL);
    }

    // MLP head on first B rows
    gemm_tc<128, true><<<gB, 256>>>(nullptr, ID_HH, ID_HL, nullptr, B, HID,
                                    W1, b1, ID_Z1, 0, -1, -1);
    zero_kernel<<<4, 256>>>(ID_SUMS, 512);
    stats_kernel<<<512, 128>>>(ID_Z1, B, 128, 0);
    bnfin_kernel<<<1, 128>>>(B, g1, be1);
    bn_kernel<<<1024, 256>>>(ID_Z1, B, 128, 0, 1, -1, ID_Z1H, ID_Z1L);

    gemm_tc<64, true><<<gB, 256>>>(nullptr, ID_Z1H, ID_Z1L, nullptr, B, HID,
                                   W2, b2, ID_Z2, 0, -1, -1);
    zero_kernel<<<4, 256>>>(ID_SUMS, 512);
    stats_kernel<<<512, 64>>>(ID_Z2, B, 64, 0);
    bnfin_kernel<<<1, 64>>>(B, g2, be2);
    bn_kernel<<<1024, 256>>>(ID_Z2, B, 64, 0, 1, ID_Z2, -1, -1);

    final_kernel<<<(B * 32 + 255) / 256, 256>>>(W3, b3, (float*)d_out, B);
}